// round 13
// baseline (speedup 1.0000x reference)
#include <cuda_runtime.h>
#include <cuda_fp16.h>
#include <cstdint>
#include <math.h>

// ============================================================================
// Globals
// ============================================================================

__device__ double g_sum[2];

// fp16 panels (pre-scaled by sqrt(log2e)), [tb = t*4+b][pos][c] layout:
#define L0_OFF 0
#define L1_OFF 2097152
__device__ __half g_scratch[3145728];

__global__ void init_sums_kernel() { g_sum[0] = 0.0; g_sum[1] = 0.0; }

// ============================================================================
// Pre-convert: fp32 [b][c][pos] -> fp16 panel [tb][pos][C], scaled by
// sqrt(log2e) so the Gram arrives pre-multiplied by log2(e): softmax exp
// becomes a raw ex2.
// ============================================================================
#define SQRT_LOG2E 1.2011224087f

template <int C>
__global__ void __launch_bounds__(256)
convert_kernel(const float* __restrict__ f1, const float* __restrict__ f2,
               int HW, int off)
{
    __shared__ float tile[C * 65];  // [c][pos0..63], padded
    const int t = blockIdx.z, b = blockIdx.y;
    const int pos0 = blockIdx.x * 64;
    const float* src = (t ? f2 : f1) + (size_t)b * C * HW;

    for (int idx = threadIdx.x; idx < C * 64; idx += 256) {
        int c = idx >> 6, p = idx & 63;
        tile[c * 65 + p] = src[(size_t)c * HW + pos0 + p];
    }
    __syncthreads();

    __half* o = g_scratch + off + ((size_t)(t * 4 + b) * HW + pos0) * C;
    constexpr int CSH = (C == 64) ? 6 : 7;
    for (int idx = threadIdx.x; idx < 64 * C; idx += 256) {
        int p = idx >> CSH, c = idx & (C - 1);
        o[(size_t)p * C + c] = __float2half(tile[c * 65 + p] * SQRT_LOG2E);
    }
}

// ============================================================================
// PTX helpers (sm_80+ vocabulary only)
// ============================================================================

__device__ __forceinline__ uint32_t smem_to_u32(const void* p) {
    uint32_t a;
    asm("{ .reg .u64 t; cvta.to.shared.u64 t, %1; cvt.u32.u64 %0, t; }"
        : "=r"(a) : "l"(p));
    return a;
}

__device__ __forceinline__ void ldmatrix_x4(uint32_t* r, uint32_t addr) {
    asm volatile(
        "ldmatrix.sync.aligned.m8n8.x4.shared.b16 {%0,%1,%2,%3}, [%4];"
        : "=r"(r[0]), "=r"(r[1]), "=r"(r[2]), "=r"(r[3]) : "r"(addr));
}

// fp16-accumulate MMA: D (2 regs of half2) += A @ B^T
__device__ __forceinline__ void mma_16816_h(uint32_t* d, const uint32_t* a,
                                            const uint32_t* b) {
    asm volatile(
        "mma.sync.aligned.m16n8k16.row.col.f16.f16.f16.f16 "
        "{%0,%1}, {%2,%3,%4,%5}, {%6,%7}, {%0,%1};"
        : "+r"(d[0]), "+r"(d[1])
        : "r"(a[0]), "r"(a[1]), "r"(a[2]), "r"(a[3]), "r"(b[0]), "r"(b[1]));
}

__device__ __forceinline__ void cp_async16(uint32_t saddr, const void* gaddr) {
    asm volatile("cp.async.cg.shared.global [%0], [%1], 16;"
                 :: "r"(saddr), "l"(gaddr));
}
#define CP_COMMIT() asm volatile("cp.async.commit_group;" ::: "memory")
#define CP_WAIT(n)  asm volatile("cp.async.wait_group %0;" :: "n"(n) : "memory")

__device__ __forceinline__ __half2 u2h(uint32_t v) {
    return *reinterpret_cast<__half2*>(&v);
}
__device__ __forceinline__ uint32_t h2u(__half2 v) {
    return *reinterpret_cast<uint32_t*>(&v);
}

// single-instruction f16x2 2^x
__device__ __forceinline__ __half2 ex2_h2(__half2 x) {
    uint32_t r, xi = h2u(x);
    asm("ex2.approx.f16x2 %0, %1;" : "=r"(r) : "r"(xi));
    return u2h(r);
}

// fast per-element reciprocal of a half2 via 2x rcp.approx.f32
__device__ __forceinline__ __half2 rcp_h2(__half2 s) {
    float lo = __low2float(s), hi = __high2float(s);
    float rlo, rhi;
    asm("rcp.approx.f32 %0, %1;" : "=f"(rlo) : "f"(lo));
    asm("rcp.approx.f32 %0, %1;" : "=f"(rhi) : "f"(hi));
    return __floats2half2_rn(rlo, rhi);
}

// ============================================================================
// Fused Gram (mma.sync fp16 acc) + two-phase f16x2 batch-softmax + |diff|.
// Block: 64(i) x 64(j) tile, triangular 1-D grid (tj >= ti).
// 512 threads = 16 warps (4 row x 4 col), warp = 16m x 16n.
// acc = 4 half2 regs per batch -> fits 64-reg cap at 2 CTAs/SM.
// ============================================================================
template <int C, int NSTAGES, int MINB>
__global__ void __launch_bounds__(512, MINB)
gram_loss_mma(int HW, int off, int level)
{
    // ---- triangular decode: blockIdx.x -> (ti, tj), tj >= ti ----
    const int k = blockIdx.x;
    int a = (int)((sqrtf(8.0f * k + 1.0f) - 1.0f) * 0.5f);
    while ((a + 1) * (a + 2) / 2 <= k) ++a;
    while (a * (a + 1) / 2 > k) --a;
    const int ti = k - a * (a + 1) / 2;   // 0..a
    const int tj = a;                     // tj >= ti

    constexpr int NCH = C / 8;                 // 16B chunks per row
    constexpr int TILE_B = (C / 64) * 8192;    // 64 rows x 2C bytes
    constexpr int STAGE_B = 2 * TILE_B;        // A | B
    constexpr int KSTEPS = C / 16;
    constexpr int NLOAD = (64 * NCH) / 512;    // cp.async iters per tile/thread

    extern __shared__ char smem[];
    const uint32_t sb = smem_to_u32(smem);
    uint32_t* aff = (uint32_t*)(smem + NSTAGES * STAGE_B);  // [b*4+r][tid] 32 KB

    const int tid = threadIdx.x, wid = tid >> 5, lid = tid & 31;
    const int wrow = wid & 3, wcol = wid >> 2;   // 4x4 warp grid
    const int i0 = ti * 64, j0 = tj * 64;

    // ---- precomputed loader offsets (combo/stage-invariant) ----
    uint32_t lo_sm[NLOAD];
    uint32_t lo_gl[NLOAD];
    #pragma unroll
    for (int p = 0; p < NLOAD; ++p) {
        const int v = p * 512 + tid;
        const int row = v / NCH, kcq = v % NCH;
        lo_sm[p] = (kcq >> 3) * 8192 + row * 128 +
                   (((kcq & 7) ^ (row & 7)) << 4);
        lo_gl[p] = row * C + kcq * 8;
    }

    const size_t HWC = (size_t)HW * C;
    auto load_stage = [&](int combo, int stage) {
        const __half* base = g_scratch + off + (size_t)combo * HWC;
        const __half* sA = base + (size_t)i0 * C;
        const __half* sB = base + (size_t)j0 * C;
        const uint32_t stb = sb + stage * STAGE_B;
        #pragma unroll
        for (int p = 0; p < NLOAD; ++p) {
            cp_async16(stb + lo_sm[p], sA + lo_gl[p]);
            cp_async16(stb + TILE_B + lo_sm[p], sB + lo_gl[p]);
        }
    };

    // ---- per-lane ldmatrix addressing (stage-invariant) ----
    const int mat = lid >> 3, lrow = lid & 7;
    const int a_row = wrow * 16 + ((mat & 1) << 3) + lrow;
    const int a_kh = mat >> 1;
    const int b_row = wcol * 16 + ((mat >> 1) << 3) + lrow;
    const int b_kh = mat & 1;
    const uint32_t a_off = a_row * 128;
    const uint32_t b_off = TILE_B + b_row * 128;
    const int a_r7 = a_row & 7, b_r7 = b_row & 7;

    load_stage(0, 0); CP_COMMIT();
    load_stage(1, 1); CP_COMMIT();

    // acc[b][r]: r = nb*2 + dreg; nb = n-block (j 0-7 / 8-15 within warp tile)
    // dreg 0 -> row gi, 1 -> row gi+8; each reg = half2 over cols (j, j+1)
    uint32_t acc[4][4];
    float wsum = 0.0f;
    const bool fullabove = (tj > ti);
    const int gi = lid >> 2, gj = (lid & 3) << 1;

    #pragma unroll 1
    for (int t = 0; t < 2; ++t) {
        #pragma unroll
        for (int b = 0; b < 4; ++b) {
            const int combo = t * 4 + b;
            if (combo == 7) { CP_WAIT(0); } else { CP_WAIT(1); }
            __syncthreads();  // combo's stage ready; prior readers done
            if (combo + 2 < 8) {
                load_stage(combo + 2, (combo + 2) % NSTAGES);
                CP_COMMIT();
            }

            const uint32_t stb = sb + (combo % NSTAGES) * STAGE_B;
            #pragma unroll
            for (int s = 0; s < 4; ++s) acc[b][s] = 0u;

            #pragma unroll
            for (int ks = 0; ks < KSTEPS; ++ks) {
                const int kb = ks >> 2, kc = (ks & 3) * 2;
                uint32_t af[4], bf[4];
                ldmatrix_x4(af, stb + a_off + kb * 8192 +
                                (((kc + a_kh) ^ a_r7) << 4));
                ldmatrix_x4(bf, stb + b_off + kb * 8192 +
                                (((kc + b_kh) ^ b_r7) << 4));
                mma_16816_h(acc[b] + 0, af, bf + 0);   // nb0 -> r0,r1
                mma_16816_h(acc[b] + 2, af, bf + 2);   // nb1 -> r2,r3
            }
        }

        // ---- per-phase f16x2 epilogue: base-2 softmax + |diff| ----
        #pragma unroll
        for (int r = 0; r < 4; ++r) {
            const __half2 A0 = u2h(acc[0][r]), A1 = u2h(acc[1][r]);
            const __half2 A2 = u2h(acc[2][r]), A3 = u2h(acc[3][r]);
            const __half2 m = __hmax2(__hmax2(A0, A1), __hmax2(A2, A3));
            const __half2 e0 = ex2_h2(__hsub2(A0, m));
            const __half2 e1 = ex2_h2(__hsub2(A1, m));
            const __half2 e2 = ex2_h2(__hsub2(A2, m));
            const __half2 e3 = ex2_h2(__hsub2(A3, m));
            const __half2 sum = __hadd2(__hadd2(e0, e1), __hadd2(e2, e3));
            const __half2 inv = rcp_h2(sum);
            const __half2 p0 = __hmul2(e0, inv), p1 = __hmul2(e1, inv);
            const __half2 p2 = __hmul2(e2, inv), p3 = __hmul2(e3, inv);

            if (t == 0) {
                aff[(0 * 4 + r) * 512 + tid] = h2u(p0);
                aff[(1 * 4 + r) * 512 + tid] = h2u(p1);
                aff[(2 * 4 + r) * 512 + tid] = h2u(p2);
                aff[(3 * 4 + r) * 512 + tid] = h2u(p3);
            } else {
                __half2 d = __habs2(__hsub2(u2h(aff[(0*4+r)*512 + tid]), p0));
                d = __hadd2(d, __habs2(__hsub2(u2h(aff[(1*4+r)*512 + tid]), p1)));
                d = __hadd2(d, __habs2(__hsub2(u2h(aff[(2*4+r)*512 + tid]), p2)));
                d = __hadd2(d, __habs2(__hsub2(u2h(aff[(3*4+r)*512 + tid]), p3)));
                const float2 dd = __half22float2(d);
                if (fullabove) {
                    wsum += dd.x + dd.y;
                } else {
                    const int i = i0 + wrow * 16 + gi + ((r & 1) << 3);
                    const int j = j0 + wcol * 16 + ((r >> 1) << 3) + gj;
                    const float wlo = (j > i) ? 2.0f : ((j == i) ? 1.0f : 0.0f);
                    const float whi = (j + 1 > i) ? 2.0f : ((j + 1 == i) ? 1.0f : 0.0f);
                    wsum += wlo * dd.x + whi * dd.y;
                }
            }
        }
    }

    // ---- reduce: warp shfl -> smem -> single atomic ----
    if (fullabove) wsum *= 2.0f;
    #pragma unroll
    for (int s2 = 16; s2; s2 >>= 1) wsum += __shfl_xor_sync(0xFFFFFFFFu, wsum, s2);
    __syncthreads();
    float* wsums = (float*)smem;
    if (lid == 0) wsums[wid] = wsum;
    __syncthreads();
    if (tid == 0) {
        float tt = 0.0f;
        #pragma unroll
        for (int wq = 0; wq < 16; ++wq) tt += wsums[wq];
        atomicAdd(&g_sum[level], (double)tt);
    }
}

__global__ void finalize_kernel(float* out) {
    const double n0 = 4.0 * 4096.0 * 4096.0;
    const double n1 = 4.0 * 1024.0 * 1024.0;
    out[0] = (float)((g_sum[0] / n0 + g_sum[1] / n1) * 0.5);
}

// ============================================================================
// Launch
// ============================================================================
extern "C" void kernel_launch(void* const* d_in, const int* in_sizes, int n_in,
                              void* d_out, int out_size)
{
    const float* fea1_0 = (const float*)d_in[0];  // (4, 64, 64, 64)
    const float* fea1_1 = (const float*)d_in[1];  // (4, 128, 32, 32)
    const float* fea2_0 = (const float*)d_in[2];
    const float* fea2_1 = (const float*)d_in[3];
    float* out = (float*)d_out;

    // smem: NSTAGES * stage + 32KB aff buffer
    const int smem0 = 3 * 16384 + 32768;    // C=64  -> 80 KB,  2 CTAs/SM
    const int smem1 = 3 * 32768 + 32768;    // C=128 -> 128 KB, 1 CTA/SM (1 wave)
    cudaFuncSetAttribute(gram_loss_mma<64, 3, 2>,
                         cudaFuncAttributeMaxDynamicSharedMemorySize, smem0);
    cudaFuncSetAttribute(gram_loss_mma<128, 3, 1>,
                         cudaFuncAttributeMaxDynamicSharedMemorySize, smem1);

    init_sums_kernel<<<1, 1>>>();

    convert_kernel<64><<<dim3(64, 4, 2), 256>>>(fea1_0, fea2_0, 4096, L0_OFF);
    convert_kernel<128><<<dim3(16, 4, 2), 256>>>(fea1_1, fea2_1, 1024, L1_OFF);

    // triangular grids: T*(T+1)/2 blocks of 64x64
    gram_loss_mma<64, 3, 2><<<64 * 65 / 2, 512, smem0>>>(4096, L0_OFF, 0);   // 2080
    gram_loss_mma<128, 3, 1><<<16 * 17 / 2, 512, smem1>>>(1024, L1_OFF, 1);  // 136

    finalize_kernel<<<1, 1>>>(out);
}